// round 15
// baseline (speedup 1.0000x reference)
#include <cuda_runtime.h>
#include <cstdint>
#include <cstddef>

// Problem constants
#define SEQ   577
#define BB    64
#define DD    768
#define HH    12
#define KK    8
#define PP    576            // SEQ-1
#define ROWS  (PP*BB)        // 36864
#define S2    (SEQ*SEQ)      // 332929
#define EPSC  1e-8f
#define BETA_C  3.0f
#define GAMMA_C 5.0f

#define DBLK  1152           // kernel D blocks: 1152*32 = 36864 rows

// ---------------- scratch (static device globals; no allocation) -------------
__device__ __align__(16) float g_fg[ROWS];
__device__ __align__(16) float g_anom[ROWS];
// global stat accumulators (zeroed by kab block 0 each launch)
__device__ double   g_n, g_s1, g_s2;
__device__ unsigned g_mxbits;

// ---------------- helpers ----------------------------------------------------
typedef unsigned long long u64;

__device__ __forceinline__ float warp_sum(float v) {
    v += __shfl_xor_sync(0xffffffffu, v, 16);
    v += __shfl_xor_sync(0xffffffffu, v, 8);
    v += __shfl_xor_sync(0xffffffffu, v, 4);
    v += __shfl_xor_sync(0xffffffffu, v, 2);
    v += __shfl_xor_sync(0xffffffffu, v, 1);
    return v;
}
__device__ __forceinline__ float warp_max(float v) {
    v = fmaxf(v, __shfl_xor_sync(0xffffffffu, v, 16));
    v = fmaxf(v, __shfl_xor_sync(0xffffffffu, v, 8));
    v = fmaxf(v, __shfl_xor_sync(0xffffffffu, v, 4));
    v = fmaxf(v, __shfl_xor_sync(0xffffffffu, v, 2));
    v = fmaxf(v, __shfl_xor_sync(0xffffffffu, v, 1));
    return v;
}
__device__ __forceinline__ u64 pk2(float lo, float hi) {
    u64 r; asm("mov.b64 %0, {%1,%2};" : "=l"(r) : "f"(lo), "f"(hi)); return r;
}
__device__ __forceinline__ void up2(u64 v, float& lo, float& hi) {
    asm("mov.b64 {%0,%1}, %2;" : "=f"(lo), "=f"(hi) : "l"(v));
}
__device__ __forceinline__ u64 f2mul(u64 a, u64 b) {
    u64 d; asm("mul.rn.f32x2 %0, %1, %2;" : "=l"(d) : "l"(a), "l"(b)); return d;
}
__device__ __forceinline__ u64 f2fma(u64 a, u64 b, u64 c) {
    u64 d; asm("fma.rn.f32x2 %0, %1, %2, %3;" : "=l"(d) : "l"(a), "l"(b), "l"(c)); return d;
}

// 8-value warp reduction: 9 shuffles. Lane ends holding full sum of cp[(lane>>2)&7].
__device__ __forceinline__ float warp_sum8(const float* cp, int lane) {
    const bool b4 = (lane & 16) != 0;
    const bool b3 = (lane & 8) != 0;
    const bool b2 = (lane & 4) != 0;
    float v0, v1, v2, v3;
    {
        float s, r;
        s = b4 ? cp[0] : cp[4]; r = __shfl_xor_sync(0xffffffffu, s, 16);
        v0 = (b4 ? cp[4] : cp[0]) + r;
        s = b4 ? cp[1] : cp[5]; r = __shfl_xor_sync(0xffffffffu, s, 16);
        v1 = (b4 ? cp[5] : cp[1]) + r;
        s = b4 ? cp[2] : cp[6]; r = __shfl_xor_sync(0xffffffffu, s, 16);
        v2 = (b4 ? cp[6] : cp[2]) + r;
        s = b4 ? cp[3] : cp[7]; r = __shfl_xor_sync(0xffffffffu, s, 16);
        v3 = (b4 ? cp[7] : cp[3]) + r;
    }
    float w0, w1;
    {
        float s, r;
        s = b3 ? v0 : v2; r = __shfl_xor_sync(0xffffffffu, s, 8);
        w0 = (b3 ? v2 : v0) + r;
        s = b3 ? v1 : v3; r = __shfl_xor_sync(0xffffffffu, s, 8);
        w1 = (b3 ? v3 : v1) + r;
    }
    float u;
    {
        float s = b2 ? w0 : w1;
        float r = __shfl_xor_sync(0xffffffffu, s, 4);
        u = (b2 ? w1 : w0) + r;
    }
    u += __shfl_xor_sync(0xffffffffu, u, 2);
    u += __shfl_xor_sync(0xffffffffu, u, 1);
    return u;
}

// ---------------- Kernel AB: fg mask + anomaly --------------------------------
// Blocks [0,64): A (fg mask), 576 thr, thread per patch. Blocks [64,64+2048):
// B (anomaly), 18 warps per block, warp per row.
__global__ void __launch_bounds__(576) kab(const float* __restrict__ x,
                                           const float* __restrict__ text,
                                           const float* __restrict__ attn) {
    const int tid = threadIdx.x;
    const int lane = tid & 31, w = tid >> 5;

    if (blockIdx.x < 64) {
        if (blockIdx.x == 0 && tid == 0) {   // reset accumulators (pre-kc1)
            g_n = 0.0; g_s1 = 0.0; g_s2 = 0.0; g_mxbits = 0u;
        }
        // ---- A: foreground mask ----
        __shared__ float sp[18];
        __shared__ float bcast;
        const int b = blockIdx.x;
        const int p = tid;

        const float* base = attn + (size_t)b * HH * (size_t)S2 + 1 + p;
        float a = 0.f;
        #pragma unroll
        for (int h = 0; h < HH; h++) a += __ldg(base + (size_t)h * S2);
        a *= (1.0f / 12.0f);

        float v = warp_sum(a);
        if (lane == 0) sp[w] = v;
        __syncthreads();
        if (w == 0) {
            float t = (lane < 18) ? sp[lane] : 0.f;
            t = warp_sum(t);
            if (lane == 0) bcast = t;
        }
        __syncthreads();
        const float mu = bcast * (1.0f / 576.0f);
        const float d = a - mu;
        __syncthreads();

        v = warp_sum(d * d);
        if (lane == 0) sp[w] = v;
        __syncthreads();
        if (w == 0) {
            float t = (lane < 18) ? sp[lane] : 0.f;
            t = warp_sum(t);
            if (lane == 0) bcast = t;
        }
        __syncthreads();
        const float sigma = sqrtf(bcast * (1.0f / 575.0f));

        g_fg[p * BB + b] = (a > mu + 1.5f * sigma) ? 1.0f : 0.0f;
    } else {
        // ---- B: per-row anomaly (warp per row) ----
        const int r = (blockIdx.x - 64) * 18 + w;
        const int b = r & (BB - 1);

        const float4* xr = (const float4*)x + (size_t)(r + BB) * (DD / 4);
        const float4* tr = (const float4*)text + (size_t)b * (DD / 4);

        float ss = 0.f, st = 0.f, tt = 0.f;
        #pragma unroll
        for (int it = 0; it < 6; it++) {
            const float4 xv = __ldg(xr + it * 32 + lane);
            const float4 tv = __ldg(tr + it * 32 + lane);
            ss += xv.x * xv.x + xv.y * xv.y + xv.z * xv.z + xv.w * xv.w;
            st += xv.x * tv.x + xv.y * tv.y + xv.z * tv.z + xv.w * tv.w;
            tt += tv.x * tv.x + tv.y * tv.y + tv.z * tv.z + tv.w * tv.w;
        }
        ss = warp_sum(ss);
        st = warp_sum(st);
        tt = warp_sum(tt);

        if (lane == 0) {
            const float pn = sqrtf(ss);
            const float tn = sqrtf(tt);
            const float sim = st / (fmaxf(pn, EPSC) * fmaxf(tn, EPSC));
            g_anom[r] = pn * (1.0f - fmaxf(sim, 0.0f));
        }
    }
}

// ---------------- Kernel C1: distributed stats + cls copy ---------------------
// 288 blocks x 128. One anomaly element per thread; first 12288 threads also
// copy the cls row (64*768 floats = 12288 float4) out[0] = x[0].
__global__ void __launch_bounds__(128) kc1(const float* __restrict__ x,
                                           float* __restrict__ out) {
    const int tid = threadIdx.x;
    const int lane = tid & 31, w = tid >> 5;
    const int i = blockIdx.x * 128 + tid;

    if (i < (BB * DD / 4))
        ((float4*)out)[i] = __ldg((const float4*)x + i);

    const float a = g_anom[i];
    const float f = g_fg[i];
    const float bg = 1.f - f;

    float n  = warp_sum(bg);
    float s1 = warp_sum(bg * a);
    float s2 = warp_sum(bg * a * a);
    float mx = warp_max(a);

    __shared__ float r0[4], r1[4], r2[4], r3[4];
    if (lane == 0) { r0[w] = n; r1[w] = s1; r2[w] = s2; r3[w] = mx; }
    __syncthreads();
    if (w == 0 && lane == 0) {
        const float bn  = r0[0] + r0[1] + r0[2] + r0[3];
        const float bs1 = r1[0] + r1[1] + r1[2] + r1[3];
        const float bs2 = r2[0] + r2[1] + r2[2] + r2[3];
        const float bmx = fmaxf(fmaxf(r3[0], r3[1]), fmaxf(r3[2], r3[3]));
        atomicAdd(&g_n,  (double)bn);
        atomicAdd(&g_s1, (double)bs1);
        atomicAdd(&g_s2, (double)bs2);
        atomicMax(&g_mxbits, __float_as_uint(fmaxf(bmx, 0.f)));
    }
}

// ---------------- Kernel D: pipelined coeff + gate + proj ----------------------
// 192 threads own 4 cols; pc in 32 regs; __launch_bounds__(192,5) caps regs at
// 68 → 5 blocks/SM. x staged in SMEM (thread-private slots). One barrier per
// 4-row batch. Gate computed in-kernel by threads 32-35 during the finalize
// slot (thr from double accumulators, computed once by tid 0 before the first
// barrier). Reverse block order for L2 reuse of x after kab.
__global__ void __launch_bounds__(192, 5) kd_out(const float* __restrict__ x,
                                                 const float* __restrict__ pc,
                                                 float* __restrict__ out) {
    const int tid = threadIdx.x;
    const int warp = tid >> 5;
    const int lane = tid & 31;

    __shared__ float redp[2][4 * 6 * 8];            // [buf][row][warp][k]
    __shared__ __align__(16) float cfin[2][4 * 8];  // [buf][row][k]
    __shared__ __align__(16) float4 xs[2][4][192];  // [buf][row][tid]  24 KB
    __shared__ float sgate[2][4];                   // [buf][row]
    __shared__ float sthr;

    if (tid == 0) {
        const double n  = g_n;
        const double s1 = g_s1;
        const double s2 = g_s2;
        const double mu = s1 / fmax(n, 1.0);
        const double var = fmax((s2 - mu * mu * n) / fmax(n - 1.0, 1.0), 0.0);
        sthr = (n > 0.0) ? (float)(mu + (double)BETA_C * sqrt(var))
                         : __uint_as_float(g_mxbits);
    }

    u64 pc0[KK], pc1[KK];
    #pragma unroll
    for (int k = 0; k < KK; k++) {
        const float4 v = __ldg((const float4*)pc + k * 192 + tid);
        pc0[k] = pk2(v.x, v.y);
        pc1[k] = pk2(v.z, v.w);
    }

    const int base = (DBLK - 1 - (int)blockIdx.x) * 32;
    const int kk = lane >> 2;
    const bool kl = (lane & 3) == 0;

    // ---- prologue: batch 0 load + partials ----
    #pragma unroll
    for (int j = 0; j < 4; j++) {
        const int r = base + j;
        const float4 xv = __ldg((const float4*)x + (size_t)(r + BB) * (DD / 4) + tid);
        xs[0][j][tid] = xv;
        const u64 x0 = pk2(xv.x, xv.y);
        const u64 x1 = pk2(xv.z, xv.w);
        float cp[KK];
        #pragma unroll
        for (int k = 0; k < KK; k++) {
            const u64 acc = f2fma(x1, pc1[k], f2mul(x0, pc0[k]));
            float lo, hi; up2(acc, lo, hi);
            cp[k] = lo + hi;
        }
        const float u = warp_sum8(cp, lane);
        if (kl) redp[0][(j * 6 + warp) * 8 + kk] = u;
    }
    __syncthreads();   // also publishes sthr
    if (tid < 32) {
        const int row = tid >> 3, k = tid & 7;
        float s = 0.f;
        #pragma unroll
        for (int ww = 0; ww < 6; ww++) s += redp[0][(row * 6 + ww) * 8 + k];
        cfin[0][row * 8 + k] = s;
    } else if (tid < 36) {
        const int j = tid - 32;
        const int r = base + j;
        const float a = __ldg(&g_anom[r]);
        const float f = __ldg(&g_fg[r]);
        sgate[0][j] = f + (1.f - f) *
                      (1.0f / (1.0f + __expf(-GAMMA_C * (sthr - a))));
    }

    // ---- main loop: batches 1..7 ----
    for (int n = 1; n < 8; n++) {
        const int pn = n & 1;
        const int i0 = n * 4;
        #pragma unroll
        for (int j = 0; j < 4; j++) {
            const int r = base + i0 + j;
            const float4 xv = __ldg((const float4*)x + (size_t)(r + BB) * (DD / 4) + tid);
            xs[pn][j][tid] = xv;
            const u64 x0 = pk2(xv.x, xv.y);
            const u64 x1 = pk2(xv.z, xv.w);
            float cp[KK];
            #pragma unroll
            for (int k = 0; k < KK; k++) {
                const u64 acc = f2fma(x1, pc1[k], f2mul(x0, pc0[k]));
                float lo, hi; up2(acc, lo, hi);
                cp[k] = lo + hi;
            }
            const float u = warp_sum8(cp, lane);
            if (kl) redp[pn][(j * 6 + warp) * 8 + kk] = u;
        }
        __syncthreads();   // redp[pn] ready; prev cfin/sgate/xs writes fenced
        if (tid < 32) {
            const int row = tid >> 3, k = tid & 7;
            float s = 0.f;
            #pragma unroll
            for (int ww = 0; ww < 6; ww++) s += redp[pn][(row * 6 + ww) * 8 + k];
            cfin[pn][row * 8 + k] = s;
        } else if (tid < 36) {
            const int j = tid - 32;
            const int r = base + i0 + j;
            const float a = __ldg(&g_anom[r]);
            const float f = __ldg(&g_fg[r]);
            sgate[pn][j] = f + (1.f - f) *
                           (1.0f / (1.0f + __expf(-GAMMA_C * (sthr - a))));
        }
        // project batch n-1 from smem-staged x (thread-private slot)
        #pragma unroll
        for (int j = 0; j < 4; j++) {
            const int r = base + (n - 1) * 4 + j;
            const float g = sgate[1 - pn][j];
            const float4 xv = xs[1 - pn][j][tid];
            const float4 cA = *(const float4*)(cfin[1 - pn] + j * 8);
            const float4 cB = *(const float4*)(cfin[1 - pn] + j * 8 + 4);

            u64 cc = pk2(cA.x, cA.x);
            u64 q0 = f2mul(cc, pc0[0]);
            u64 q1 = f2mul(cc, pc1[0]);
            cc = pk2(cA.y, cA.y); q0 = f2fma(cc, pc0[1], q0); q1 = f2fma(cc, pc1[1], q1);
            cc = pk2(cA.z, cA.z); q0 = f2fma(cc, pc0[2], q0); q1 = f2fma(cc, pc1[2], q1);
            cc = pk2(cA.w, cA.w); q0 = f2fma(cc, pc0[3], q0); q1 = f2fma(cc, pc1[3], q1);
            cc = pk2(cB.x, cB.x); q0 = f2fma(cc, pc0[4], q0); q1 = f2fma(cc, pc1[4], q1);
            cc = pk2(cB.y, cB.y); q0 = f2fma(cc, pc0[5], q0); q1 = f2fma(cc, pc1[5], q1);
            cc = pk2(cB.z, cB.z); q0 = f2fma(cc, pc0[6], q0); q1 = f2fma(cc, pc1[6], q1);
            cc = pk2(cB.w, cB.w); q0 = f2fma(cc, pc0[7], q0); q1 = f2fma(cc, pc1[7], q1);

            const u64 x0 = pk2(xv.x, xv.y);
            const u64 x1 = pk2(xv.z, xv.w);
            const float og = 1.0f - g;
            const u64 g2  = pk2(g, g);
            const u64 og2 = pk2(og, og);
            const u64 o0 = f2fma(g2, x0, f2mul(og2, q0));
            const u64 o1 = f2fma(g2, x1, f2mul(og2, q1));
            float a0, a1, a2, a3;
            up2(o0, a0, a1);
            up2(o1, a2, a3);
            ((float4*)out)[(size_t)(r + BB) * (DD / 4) + tid] =
                make_float4(a0, a1, a2, a3);
        }
    }

    // ---- epilogue: batch 7 (cfin[1]/sgate[1]/xs[1] finalized after sync) ----
    __syncthreads();
    #pragma unroll
    for (int j = 0; j < 4; j++) {
        const int r = base + 28 + j;
        const float g = sgate[1][j];
        const float4 xv = xs[1][j][tid];
        const float4 cA = *(const float4*)(cfin[1] + j * 8);
        const float4 cB = *(const float4*)(cfin[1] + j * 8 + 4);

        u64 cc = pk2(cA.x, cA.x);
        u64 q0 = f2mul(cc, pc0[0]);
        u64 q1 = f2mul(cc, pc1[0]);
        cc = pk2(cA.y, cA.y); q0 = f2fma(cc, pc0[1], q0); q1 = f2fma(cc, pc1[1], q1);
        cc = pk2(cA.z, cA.z); q0 = f2fma(cc, pc0[2], q0); q1 = f2fma(cc, pc1[2], q1);
        cc = pk2(cA.w, cA.w); q0 = f2fma(cc, pc0[3], q0); q1 = f2fma(cc, pc1[3], q1);
        cc = pk2(cB.x, cB.x); q0 = f2fma(cc, pc0[4], q0); q1 = f2fma(cc, pc1[4], q1);
        cc = pk2(cB.y, cB.y); q0 = f2fma(cc, pc0[5], q0); q1 = f2fma(cc, pc1[5], q1);
        cc = pk2(cB.z, cB.z); q0 = f2fma(cc, pc0[6], q0); q1 = f2fma(cc, pc1[6], q1);
        cc = pk2(cB.w, cB.w); q0 = f2fma(cc, pc0[7], q0); q1 = f2fma(cc, pc1[7], q1);

        const u64 x0 = pk2(xv.x, xv.y);
        const u64 x1 = pk2(xv.z, xv.w);
        const float og = 1.0f - g;
        const u64 g2  = pk2(g, g);
        const u64 og2 = pk2(og, og);
        const u64 o0 = f2fma(g2, x0, f2mul(og2, q0));
        const u64 o1 = f2fma(g2, x1, f2mul(og2, q1));
        float a0, a1, a2, a3;
        up2(o0, a0, a1);
        up2(o1, a2, a3);
        ((float4*)out)[(size_t)(r + BB) * (DD / 4) + tid] =
            make_float4(a0, a1, a2, a3);
    }
}

// ---------------- launch ------------------------------------------------------
extern "C" void kernel_launch(void* const* d_in, const int* in_sizes, int n_in,
                              void* d_out, int out_size) {
    const float* x    = (const float*)d_in[0];
    const float* attn = (const float*)d_in[1];
    const float* text = (const float*)d_in[2];
    const float* pc   = (const float*)d_in[3];
    float* out = (float*)d_out;

    kab<<<64 + 2048, 576>>>(x, text, attn);
    kc1<<<ROWS / 128, 128>>>(x, out);     // stats + cls-row copy
    kd_out<<<DBLK, 192>>>(x, pc, out);
}

// round 17
// speedup vs baseline: 1.1200x; 1.1200x over previous
#include <cuda_runtime.h>
#include <cstdint>
#include <cstddef>

// Problem constants
#define SEQ   577
#define BB    64
#define DD    768
#define HH    12
#define KK    8
#define PP    576            // SEQ-1
#define ROWS  (PP*BB)        // 36864
#define S2    (SEQ*SEQ)      // 332929
#define EPSC  1e-8f
#define BETA_C  3.0f
#define GAMMA_C 5.0f

#define DBLK  1152           // kernel D blocks: 1152*32 = 36864 rows

// ---------------- scratch (static device globals; no allocation) -------------
__device__ __align__(16) float g_fg[ROWS];
__device__ __align__(16) float g_anom[ROWS];
// global stat accumulators (zeroed by kab block 0 each launch)
__device__ double   g_n, g_s1, g_s2;
__device__ unsigned g_mxbits;

// ---------------- helpers ----------------------------------------------------
typedef unsigned long long u64;

__device__ __forceinline__ float warp_sum(float v) {
    v += __shfl_xor_sync(0xffffffffu, v, 16);
    v += __shfl_xor_sync(0xffffffffu, v, 8);
    v += __shfl_xor_sync(0xffffffffu, v, 4);
    v += __shfl_xor_sync(0xffffffffu, v, 2);
    v += __shfl_xor_sync(0xffffffffu, v, 1);
    return v;
}
__device__ __forceinline__ float warp_max(float v) {
    v = fmaxf(v, __shfl_xor_sync(0xffffffffu, v, 16));
    v = fmaxf(v, __shfl_xor_sync(0xffffffffu, v, 8));
    v = fmaxf(v, __shfl_xor_sync(0xffffffffu, v, 4));
    v = fmaxf(v, __shfl_xor_sync(0xffffffffu, v, 2));
    v = fmaxf(v, __shfl_xor_sync(0xffffffffu, v, 1));
    return v;
}
__device__ __forceinline__ u64 pk2(float lo, float hi) {
    u64 r; asm("mov.b64 %0, {%1,%2};" : "=l"(r) : "f"(lo), "f"(hi)); return r;
}
__device__ __forceinline__ void up2(u64 v, float& lo, float& hi) {
    asm("mov.b64 {%0,%1}, %2;" : "=f"(lo), "=f"(hi) : "l"(v));
}
__device__ __forceinline__ u64 f2mul(u64 a, u64 b) {
    u64 d; asm("mul.rn.f32x2 %0, %1, %2;" : "=l"(d) : "l"(a), "l"(b)); return d;
}
__device__ __forceinline__ u64 f2fma(u64 a, u64 b, u64 c) {
    u64 d; asm("fma.rn.f32x2 %0, %1, %2, %3;" : "=l"(d) : "l"(a), "l"(b), "l"(c)); return d;
}

// 8-value warp reduction: 9 shuffles. Lane ends holding full sum of cp[(lane>>2)&7].
__device__ __forceinline__ float warp_sum8(const float* cp, int lane) {
    const bool b4 = (lane & 16) != 0;
    const bool b3 = (lane & 8) != 0;
    const bool b2 = (lane & 4) != 0;
    float v0, v1, v2, v3;
    {
        float s, r;
        s = b4 ? cp[0] : cp[4]; r = __shfl_xor_sync(0xffffffffu, s, 16);
        v0 = (b4 ? cp[4] : cp[0]) + r;
        s = b4 ? cp[1] : cp[5]; r = __shfl_xor_sync(0xffffffffu, s, 16);
        v1 = (b4 ? cp[5] : cp[1]) + r;
        s = b4 ? cp[2] : cp[6]; r = __shfl_xor_sync(0xffffffffu, s, 16);
        v2 = (b4 ? cp[6] : cp[2]) + r;
        s = b4 ? cp[3] : cp[7]; r = __shfl_xor_sync(0xffffffffu, s, 16);
        v3 = (b4 ? cp[7] : cp[3]) + r;
    }
    float w0, w1;
    {
        float s, r;
        s = b3 ? v0 : v2; r = __shfl_xor_sync(0xffffffffu, s, 8);
        w0 = (b3 ? v2 : v0) + r;
        s = b3 ? v1 : v3; r = __shfl_xor_sync(0xffffffffu, s, 8);
        w1 = (b3 ? v3 : v1) + r;
    }
    float u;
    {
        float s = b2 ? w0 : w1;
        float r = __shfl_xor_sync(0xffffffffu, s, 4);
        u = (b2 ? w1 : w0) + r;
    }
    u += __shfl_xor_sync(0xffffffffu, u, 2);
    u += __shfl_xor_sync(0xffffffffu, u, 1);
    return u;
}

// ---------------- Kernel AB: fg mask + anomaly --------------------------------
// Blocks [0,64): A (fg mask), 576 thr, thread per patch. Blocks [64,64+2048):
// B (anomaly), 18 warps per block, warp per row.
__global__ void __launch_bounds__(576) kab(const float* __restrict__ x,
                                           const float* __restrict__ text,
                                           const float* __restrict__ attn) {
    const int tid = threadIdx.x;
    const int lane = tid & 31, w = tid >> 5;

    if (blockIdx.x < 64) {
        if (blockIdx.x == 0 && tid == 0) {   // reset accumulators (pre-kc1)
            g_n = 0.0; g_s1 = 0.0; g_s2 = 0.0; g_mxbits = 0u;
        }
        // ---- A: foreground mask ----
        __shared__ float sp[18];
        __shared__ float bcast;
        const int b = blockIdx.x;
        const int p = tid;

        const float* base = attn + (size_t)b * HH * (size_t)S2 + 1 + p;
        float a = 0.f;
        #pragma unroll
        for (int h = 0; h < HH; h++) a += __ldg(base + (size_t)h * S2);
        a *= (1.0f / 12.0f);

        float v = warp_sum(a);
        if (lane == 0) sp[w] = v;
        __syncthreads();
        if (w == 0) {
            float t = (lane < 18) ? sp[lane] : 0.f;
            t = warp_sum(t);
            if (lane == 0) bcast = t;
        }
        __syncthreads();
        const float mu = bcast * (1.0f / 576.0f);
        const float d = a - mu;
        __syncthreads();

        v = warp_sum(d * d);
        if (lane == 0) sp[w] = v;
        __syncthreads();
        if (w == 0) {
            float t = (lane < 18) ? sp[lane] : 0.f;
            t = warp_sum(t);
            if (lane == 0) bcast = t;
        }
        __syncthreads();
        const float sigma = sqrtf(bcast * (1.0f / 575.0f));

        g_fg[p * BB + b] = (a > mu + 1.5f * sigma) ? 1.0f : 0.0f;
    } else {
        // ---- B: per-row anomaly (warp per row) ----
        const int r = (blockIdx.x - 64) * 18 + w;
        const int b = r & (BB - 1);

        const float4* xr = (const float4*)x + (size_t)(r + BB) * (DD / 4);
        const float4* tr = (const float4*)text + (size_t)b * (DD / 4);

        float ss = 0.f, st = 0.f, tt = 0.f;
        #pragma unroll
        for (int it = 0; it < 6; it++) {
            const float4 xv = __ldg(xr + it * 32 + lane);
            const float4 tv = __ldg(tr + it * 32 + lane);
            ss += xv.x * xv.x + xv.y * xv.y + xv.z * xv.z + xv.w * xv.w;
            st += xv.x * tv.x + xv.y * tv.y + xv.z * tv.z + xv.w * tv.w;
            tt += tv.x * tv.x + tv.y * tv.y + tv.z * tv.z + tv.w * tv.w;
        }
        ss = warp_sum(ss);
        st = warp_sum(st);
        tt = warp_sum(tt);

        if (lane == 0) {
            const float pn = sqrtf(ss);
            const float tn = sqrtf(tt);
            const float sim = st / (fmaxf(pn, EPSC) * fmaxf(tn, EPSC));
            g_anom[r] = pn * (1.0f - fmaxf(sim, 0.0f));
        }
    }
}

// ---------------- Kernel C1: distributed stats + cls copy ---------------------
// 288 blocks x 128. One anomaly element per thread; first 12288 threads also
// copy the cls row (64*768 floats = 12288 float4) out[0] = x[0].
__global__ void __launch_bounds__(128) kc1(const float* __restrict__ x,
                                           float* __restrict__ out) {
    const int tid = threadIdx.x;
    const int lane = tid & 31, w = tid >> 5;
    const int i = blockIdx.x * 128 + tid;

    if (i < (BB * DD / 4))
        ((float4*)out)[i] = __ldg((const float4*)x + i);

    const float a = g_anom[i];
    const float f = g_fg[i];
    const float bg = 1.f - f;

    float n  = warp_sum(bg);
    float s1 = warp_sum(bg * a);
    float s2 = warp_sum(bg * a * a);
    float mx = warp_max(a);

    __shared__ float r0[4], r1[4], r2[4], r3[4];
    if (lane == 0) { r0[w] = n; r1[w] = s1; r2[w] = s2; r3[w] = mx; }
    __syncthreads();
    if (w == 0 && lane == 0) {
        const float bn  = r0[0] + r0[1] + r0[2] + r0[3];
        const float bs1 = r1[0] + r1[1] + r1[2] + r1[3];
        const float bs2 = r2[0] + r2[1] + r2[2] + r2[3];
        const float bmx = fmaxf(fmaxf(r3[0], r3[1]), fmaxf(r3[2], r3[3]));
        atomicAdd(&g_n,  (double)bn);
        atomicAdd(&g_s1, (double)bs1);
        atomicAdd(&g_s2, (double)bs2);
        atomicMax(&g_mxbits, __float_as_uint(fmaxf(bmx, 0.f)));
    }
}

// ---------------- Kernel D: cp.async-pipelined coeff + gate + proj -------------
// 192 threads own 4 cols; pc in 32 regs. x prefetched into a 3-deep smem ring
// via cp.async.cg (16B/thread), issued ~1.5 batches ahead. Every xs slot is
// THREAD-PRIVATE (each thread cp.asyncs and reads only its own 16B), so ring
// reuse needs no barriers — per-thread order + wait_group suffice. One
// __syncthreads per 4-row batch guards redp/cfin/sgate only. Gate computed
// in-kernel (threads 32-35) from the double accumulators. Reverse block order
// for L2 reuse of x after kab. No forced occupancy bound (R15 lesson).
__global__ void __launch_bounds__(192) kd_out(const float* __restrict__ x,
                                              const float* __restrict__ pc,
                                              float* __restrict__ out) {
    const int tid = threadIdx.x;
    const int warp = tid >> 5;
    const int lane = tid & 31;

    __shared__ float redp[2][4 * 6 * 8];            // [buf][row][warp][k]
    __shared__ __align__(16) float cfin[2][4 * 8];  // [buf][row][k]
    __shared__ __align__(16) float4 xs[3][4][192];  // ring [slot][row][tid] 36 KB
    __shared__ float sgate[2][4];                   // [buf][row]
    __shared__ float sthr;

    const int base = (DBLK - 1 - (int)blockIdx.x) * 32;
    const uint32_t xs_addr = (uint32_t)__cvta_generic_to_shared(&xs[0][0][0]);
    const float4* xg = (const float4*)x;

    // issue one 4-row batch of cp.async (thread's own 16B per row) + commit
    #define ISSUE_BATCH(b)                                                      \
        do {                                                                    \
            const int _sl = (b) % 3;                                            \
            _Pragma("unroll")                                                   \
            for (int _j = 0; _j < 4; _j++) {                                    \
                const int _r = base + (b) * 4 + _j;                             \
                const uint32_t _sa = xs_addr +                                  \
                    (uint32_t)(((_sl * 4 + _j) * 192 + tid) * 16);              \
                const float4* _gp = xg + (size_t)(_r + BB) * (DD / 4) + tid;    \
                asm volatile("cp.async.cg.shared.global [%0], [%1], 16;"        \
                             :: "r"(_sa), "l"(_gp) : "memory");                 \
            }                                                                   \
            asm volatile("cp.async.commit_group;" ::: "memory");                \
        } while (0)

    // prefetch batches 0 and 1 immediately (DRAM starts before pc loads)
    ISSUE_BATCH(0);
    ISSUE_BATCH(1);

    if (tid == 0) {
        const double n  = g_n;
        const double s1 = g_s1;
        const double s2 = g_s2;
        const double mu = s1 / fmax(n, 1.0);
        const double var = fmax((s2 - mu * mu * n) / fmax(n - 1.0, 1.0), 0.0);
        sthr = (n > 0.0) ? (float)(mu + (double)BETA_C * sqrt(var))
                         : __uint_as_float(g_mxbits);
    }

    u64 pc0[KK], pc1[KK];
    #pragma unroll
    for (int k = 0; k < KK; k++) {
        const float4 v = __ldg((const float4*)pc + k * 192 + tid);
        pc0[k] = pk2(v.x, v.y);
        pc1[k] = pk2(v.z, v.w);
    }

    const int kk = lane >> 2;
    const bool kl = (lane & 3) == 0;

    // ---- prologue: batch 0 partials ----
    asm volatile("cp.async.wait_group 1;" ::: "memory");   // batch 0 landed
    ISSUE_BATCH(2);                                        // slot 2: untouched
    #pragma unroll
    for (int j = 0; j < 4; j++) {
        const float4 xv = xs[0][j][tid];
        const u64 x0 = pk2(xv.x, xv.y);
        const u64 x1 = pk2(xv.z, xv.w);
        float cp[KK];
        #pragma unroll
        for (int k = 0; k < KK; k++) {
            const u64 acc = f2fma(x1, pc1[k], f2mul(x0, pc0[k]));
            float lo, hi; up2(acc, lo, hi);
            cp[k] = lo + hi;
        }
        const float u = warp_sum8(cp, lane);
        if (kl) redp[0][(j * 6 + warp) * 8 + kk] = u;
    }
    __syncthreads();   // publishes sthr + redp[0]
    if (tid < 32) {
        const int row = tid >> 3, k = tid & 7;
        float s = 0.f;
        #pragma unroll
        for (int ww = 0; ww < 6; ww++) s += redp[0][(row * 6 + ww) * 8 + k];
        cfin[0][row * 8 + k] = s;
    } else if (tid < 36) {
        const int j = tid - 32;
        const int r = base + j;
        const float a = __ldg(&g_anom[r]);
        const float f = __ldg(&g_fg[r]);
        sgate[0][j] = f + (1.f - f) *
                      (1.0f / (1.0f + __expf(-GAMMA_C * (sthr - a))));
    }

    // ---- main loop: batches 1..7 ----
    for (int n = 1; n < 8; n++) {
        const int pn = n & 1;
        const int sl = n % 3;
        const int slp = (n - 1) % 3;
        const int i0 = n * 4;

        if (n == 7) asm volatile("cp.async.wait_group 0;" ::: "memory");
        else        asm volatile("cp.async.wait_group 1;" ::: "memory");

        // partials for batch n (LDS from private slot)
        #pragma unroll
        for (int j = 0; j < 4; j++) {
            const float4 xv = xs[sl][j][tid];
            const u64 x0 = pk2(xv.x, xv.y);
            const u64 x1 = pk2(xv.z, xv.w);
            float cp[KK];
            #pragma unroll
            for (int k = 0; k < KK; k++) {
                const u64 acc = f2fma(x1, pc1[k], f2mul(x0, pc0[k]));
                float lo, hi; up2(acc, lo, hi);
                cp[k] = lo + hi;
            }
            const float u = warp_sum8(cp, lane);
            if (kl) redp[pn][(j * 6 + warp) * 8 + kk] = u;
        }
        __syncthreads();   // redp[pn] ready; prev cfin/sgate reads complete
        if (tid < 32) {
            const int row = tid >> 3, k = tid & 7;
            float s = 0.f;
            #pragma unroll
            for (int ww = 0; ww < 6; ww++) s += redp[pn][(row * 6 + ww) * 8 + k];
            cfin[pn][row * 8 + k] = s;
        } else if (tid < 36) {
            const int j = tid - 32;
            const int r = base + i0 + j;
            const float a = __ldg(&g_anom[r]);
            const float f = __ldg(&g_fg[r]);
            sgate[pn][j] = f + (1.f - f) *
                           (1.0f / (1.0f + __expf(-GAMMA_C * (sthr - a))));
        }
        // project batch n-1 from smem slot slp (thread-private reads)
        #pragma unroll
        for (int j = 0; j < 4; j++) {
            const int r = base + (n - 1) * 4 + j;
            const float g = sgate[1 - pn][j];
            const float4 xv = xs[slp][j][tid];
            const float4 cA = *(const float4*)(cfin[1 - pn] + j * 8);
            const float4 cB = *(const float4*)(cfin[1 - pn] + j * 8 + 4);

            u64 cc = pk2(cA.x, cA.x);
            u64 q0 = f2mul(cc, pc0[0]);
            u64 q1 = f2mul(cc, pc1[0]);
            cc = pk2(cA.y, cA.y); q0 = f2fma(cc, pc0[1], q0); q1 = f2fma(cc, pc1[1], q1);
            cc = pk2(cA.z, cA.z); q0 = f2fma(cc, pc0[2], q0); q1 = f2fma(cc, pc1[2], q1);
            cc = pk2(cA.w, cA.w); q0 = f2fma(cc, pc0[3], q0); q1 = f2fma(cc, pc1[3], q1);
            cc = pk2(cB.x, cB.x); q0 = f2fma(cc, pc0[4], q0); q1 = f2fma(cc, pc1[4], q1);
            cc = pk2(cB.y, cB.y); q0 = f2fma(cc, pc0[5], q0); q1 = f2fma(cc, pc1[5], q1);
            cc = pk2(cB.z, cB.z); q0 = f2fma(cc, pc0[6], q0); q1 = f2fma(cc, pc1[6], q1);
            cc = pk2(cB.w, cB.w); q0 = f2fma(cc, pc0[7], q0); q1 = f2fma(cc, pc1[7], q1);

            const u64 x0 = pk2(xv.x, xv.y);
            const u64 x1 = pk2(xv.z, xv.w);
            const float og = 1.0f - g;
            const u64 g2  = pk2(g, g);
            const u64 og2 = pk2(og, og);
            const u64 o0 = f2fma(g2, x0, f2mul(og2, q0));
            const u64 o1 = f2fma(g2, x1, f2mul(og2, q1));
            float a0, a1, a2, a3;
            up2(o0, a0, a1);
            up2(o1, a2, a3);
            ((float4*)out)[(size_t)(r + BB) * (DD / 4) + tid] =
                make_float4(a0, a1, a2, a3);
        }
        // prefetch batch n+2 into slot (n+2)%3 == (n-1)%3 — its last reader
        // (projection of batch n-1, this thread, above) has completed.
        if (n < 6) ISSUE_BATCH(n + 2);
    }

    // ---- epilogue: batch 7 (cfin[1]/sgate[1] finalized after last sync) ----
    __syncthreads();
    #pragma unroll
    for (int j = 0; j < 4; j++) {
        const int r = base + 28 + j;
        const float g = sgate[1][j];
        const float4 xv = xs[7 % 3][j][tid];
        const float4 cA = *(const float4*)(cfin[1] + j * 8);
        const float4 cB = *(const float4*)(cfin[1] + j * 8 + 4);

        u64 cc = pk2(cA.x, cA.x);
        u64 q0 = f2mul(cc, pc0[0]);
        u64 q1 = f2mul(cc, pc1[0]);
        cc = pk2(cA.y, cA.y); q0 = f2fma(cc, pc0[1], q0); q1 = f2fma(cc, pc1[1], q1);
        cc = pk2(cA.z, cA.z); q0 = f2fma(cc, pc0[2], q0); q1 = f2fma(cc, pc1[2], q1);
        cc = pk2(cA.w, cA.w); q0 = f2fma(cc, pc0[3], q0); q1 = f2fma(cc, pc1[3], q1);
        cc = pk2(cB.x, cB.x); q0 = f2fma(cc, pc0[4], q0); q1 = f2fma(cc, pc1[4], q1);
        cc = pk2(cB.y, cB.y); q0 = f2fma(cc, pc0[5], q0); q1 = f2fma(cc, pc1[5], q1);
        cc = pk2(cB.z, cB.z); q0 = f2fma(cc, pc0[6], q0); q1 = f2fma(cc, pc1[6], q1);
        cc = pk2(cB.w, cB.w); q0 = f2fma(cc, pc0[7], q0); q1 = f2fma(cc, pc1[7], q1);

        const u64 x0 = pk2(xv.x, xv.y);
        const u64 x1 = pk2(xv.z, xv.w);
        const float og = 1.0f - g;
        const u64 g2  = pk2(g, g);
        const u64 og2 = pk2(og, og);
        const u64 o0 = f2fma(g2, x0, f2mul(og2, q0));
        const u64 o1 = f2fma(g2, x1, f2mul(og2, q1));
        float a0, a1, a2, a3;
        up2(o0, a0, a1);
        up2(o1, a2, a3);
        ((float4*)out)[(size_t)(r + BB) * (DD / 4) + tid] =
            make_float4(a0, a1, a2, a3);
    }
    #undef ISSUE_BATCH
}

// ---------------- launch ------------------------------------------------------
extern "C" void kernel_launch(void* const* d_in, const int* in_sizes, int n_in,
                              void* d_out, int out_size) {
    const float* x    = (const float*)d_in[0];
    const float* attn = (const float*)d_in[1];
    const float* text = (const float*)d_in[2];
    const float* pc   = (const float*)d_in[3];
    float* out = (float*)d_out;

    kab<<<64 + 2048, 576>>>(x, text, attn);
    kc1<<<ROWS / 128, 128>>>(x, out);     // stats + cls-row copy
    kd_out<<<DBLK, 192>>>(x, pc, out);
}